// round 12
// baseline (speedup 1.0000x reference)
#include <cuda_runtime.h>
#include <cstdint>

// Problem constants
#define NPTS 100000
#define CIN  16
#define FOUT 16
#define BW   8
#define NDIM 3
#define NSEG 8192

// Pre-conv (fp16 mma.sync m16n8k16) tiling — persistent + double-buffered
#define PN    32                  // points per tile -> 256 output rows
#define T1    256                 // 8 warps; warp covers 32 rows (2 m16 tiles)
#define NTILE (NPTS / PN)         // 3125
#define TPC   5                   // tiles per CTA
#define NBX   (NTILE / TPC)       // 625
#define XS_WORDS (34 * 10 * 8)    // 2720 per buffer
#define WB_WORDS (144 * 8)        // 1152
#define GTASKS   (34 * 8 * 4)     // 1088 gather lane-tasks per tile

__device__ __forceinline__ uint32_t pack_f16x2(float lo, float hi) {
    uint32_t r;
    asm("cvt.rn.f16x2.f32 %0, %1, %2;" : "=r"(r) : "f"(hi), "f"(lo));
    return r;
}

#define MMA_F16(acc, a0, a1, a2, a3, b0, b1)                                   \
    asm("mma.sync.aligned.m16n8k16.row.col.f32.f16.f16.f32 "                   \
        "{%0,%1,%2,%3},{%4,%5,%6,%7},{%8,%9},{%0,%1,%2,%3};"                   \
        : "+f"(acc[0]), "+f"(acc[1]), "+f"(acc[2]), "+f"(acc[3])               \
        : "r"(a0), "r"(a1), "r"(a2), "r"(a3), "r"(b0), "r"(b1))

// Device scratch (static allocation — no cudaMalloc allowed)
__device__ float    g_seg[NDIM * NSEG * BW * FOUT];   // segment sums
__device__ float    g_z  [NDIM * NSEG * BW * FOUT];   // post-conv output
__device__ uint32_t g_wb [NDIM * WB_WORDS];           // permuted fp16 weights
__device__ float    g_bs [NDIM * FOUT];               // bias

// ---------------------------------------------------------------------------
// Kernel 0: zero the segment-sum scratch
// ---------------------------------------------------------------------------
__global__ void zero_seg_kernel() {
    const int total = NDIM * NSEG * BW * FOUT / 4;
    float4* p = reinterpret_cast<float4*>(g_seg);
    const float4 z = make_float4(0.f, 0.f, 0.f, 0.f);
    for (int i = blockIdx.x * blockDim.x + threadIdx.x; i < total;
         i += gridDim.x * blockDim.x)
        p[i] = z;
}

// ---------------------------------------------------------------------------
// Kernel 0b: permute + convert pre-conv weights to fp16 once.
// Storage row s = nt*8+n holds filter 4*(n>>1)+2*nt+(n&1); word j holds
// channel pair (c, c+1), c = j odd ? j+7 : j.
// ---------------------------------------------------------------------------
__global__ void weight_setup_kernel(const float* __restrict__ pre_w,
                                    const float* __restrict__ pre_b) {
    for (int gi = blockIdx.x * blockDim.x + threadIdx.x; gi < NDIM * WB_WORDS;
         gi += gridDim.x * blockDim.x) {
        const int d   = gi / WB_WORDS;
        const int i   = gi - d * WB_WORDS;
        const int tap = i >> 7;
        const int rem = i & 127;
        const int s   = rem >> 3;
        const int j   = rem & 7;
        const int nt  = s >> 3;
        const int n   = s & 7;
        const int fpm = 4 * (n >> 1) + 2 * nt + (n & 1);
        const int c   = (j & 1) ? (j + 7) : j;
        const int base = d * 2304 + tap * 256;
        g_wb[gi] = pack_f16x2(pre_w[base + c * 16 + fpm],
                              pre_w[base + (c + 1) * 16 + fpm]);
    }
    const int t = blockIdx.x * blockDim.x + threadIdx.x;
    if (t < NDIM * FOUT) g_bs[t] = pre_b[t];
}

// ---------------------------------------------------------------------------
// Kernel 1: persistent double-buffered pre-conv.
// grid (625, 3), block 256; each CTA runs 5 tiles, prefetching tile t+1's X
// rows into registers while tile t's MMA + epilogue execute. ONE sync/tile.
// ---------------------------------------------------------------------------
struct Pref { float4 v[5]; };

__device__ __forceinline__ void prefetch_tile(
    const float* __restrict__ X, const int* __restrict__ inv,
    int d, int bstart, int tid, Pref& P)
{
#pragma unroll
    for (int k = 0; k < 5; ++k) {
        const int i = k * T1 + tid;
        P.v[k] = make_float4(0.f, 0.f, 0.f, 0.f);
        if (i < GTASKS) {
            const int r  = i >> 2;
            const int tq = i & 3;
            const int pt = r >> 3;
            const int w  = r & 7;
            const int gp = bstart - 1 + pt;
            if ((unsigned)gp < NPTS) {
                const int idx = inv[(d * NPTS + gp) * BW + w];
                P.v[k] = reinterpret_cast<const float4*>(X)[idx * 4 + tq];
            }
        }
    }
}

__device__ __forceinline__ void store_tile(uint32_t* xs, int tid, const Pref& P)
{
#pragma unroll
    for (int k = 0; k < 5; ++k) {
        const int i = k * T1 + tid;
        if (i < GTASKS) {
            const int r  = i >> 2;
            const int tq = i & 3;
            const int pt = r >> 3;
            const int w  = r & 7;
            const int woff = (pt * 10 + w + 1) * 8 + 4 * (tq & 1) + (tq >> 1);
            xs[woff]     = pack_f16x2(P.v[k].x, P.v[k].y);
            xs[woff + 2] = pack_f16x2(P.v[k].z, P.v[k].w);
        }
    }
}

__global__ void __launch_bounds__(T1)
pre_conv_mma_kernel(const float* __restrict__ X, const int* __restrict__ inv,
                    const int* __restrict__ index)
{
    __shared__ uint32_t xs[2][XS_WORDS];
    __shared__ uint32_t wb[WB_WORDS];
    __shared__ float    bs[16];

    const int tid  = threadIdx.x;
    const int wid  = tid >> 5;
    const int lane = tid & 31;
    const int q    = lane & 3;
    const int lr   = lane >> 2;
    const int d    = blockIdx.y;

    // One-time: coalesced weight/bias load + pad-slot zeroing (both buffers)
    {
        const uint4* src = reinterpret_cast<const uint4*>(g_wb + d * WB_WORDS);
        uint4* dst = reinterpret_cast<uint4*>(wb);
        for (int i = tid; i < WB_WORDS / 4; i += T1) dst[i] = src[i];
        if (tid < FOUT) bs[tid] = g_bs[d * FOUT + tid];
        for (int i = tid; i < 34 * 16; i += T1) {
            const int pt = i >> 4, rem = i & 15;
            const int wslot = (rem < 8) ? 0 : 9;
            xs[0][(pt * 10 + wslot) * 8 + (rem & 7)] = 0u;
            xs[1][(pt * 10 + wslot) * 8 + (rem & 7)] = 0u;
        }
    }

    // Prologue: gather tile 0 into buffer 0
    {
        Pref P;
        prefetch_tile(X, inv, d, blockIdx.x * PN, tid, P);
        store_tile(xs[0], tid, P);
    }
    __syncthreads();

    const float b0v = bs[4 * q + 0], b1v = bs[4 * q + 1];
    const float b2v = bs[4 * q + 2], b3v = bs[4 * q + 3];

    int base_lo[2], base_hi[2];
#pragma unroll
    for (int mt = 0; mt < 2; ++mt) {
        const int ptl = wid * 4 + mt * 2;
        base_lo[mt] = (ptl * 10 + lr) * 8 + 2 * q;
        base_hi[mt] = base_lo[mt] + 80;
    }

    int cur = 0;
#pragma unroll 1
    for (int t = 0; t < TPC; ++t) {
        const int bstart = (blockIdx.x + NBX * t) * PN;

        // Prefetch tile t+1's X rows into registers (latency hidden by MMA)
        Pref P;
        if (t < TPC - 1)
            prefetch_tile(X, inv, d, (blockIdx.x + NBX * (t + 1)) * PN, tid, P);

        // MMA on current buffer
        float acc[2][2][4];
#pragma unroll
        for (int mt = 0; mt < 2; ++mt)
#pragma unroll
            for (int nt = 0; nt < 2; ++nt)
#pragma unroll
                for (int i = 0; i < 4; ++i) acc[mt][nt][i] = 0.f;

        const uint32_t* xb = xs[cur];
#pragma unroll
        for (int a = 0; a < 3; ++a) {
#pragma unroll
            for (int b = 0; b < 3; ++b) {
                const int tap  = a * 3 + b;
                const int toff = (a * 10 + b) * 8;
                const uint2 bf0 = *reinterpret_cast<const uint2*>(
                    wb + (tap * 16 + lr) * 8 + 2 * q);
                const uint2 bf1 = *reinterpret_cast<const uint2*>(
                    wb + (tap * 16 + 8 + lr) * 8 + 2 * q);
#pragma unroll
                for (int mt = 0; mt < 2; ++mt) {
                    const uint2 alo = *reinterpret_cast<const uint2*>(
                        xb + base_lo[mt] + toff);
                    const uint2 ahi = *reinterpret_cast<const uint2*>(
                        xb + base_hi[mt] + toff);
                    MMA_F16(acc[mt][0], alo.x, ahi.x, alo.y, ahi.y, bf0.x, bf0.y);
                    MMA_F16(acc[mt][1], alo.x, ahi.x, alo.y, ahi.y, bf1.x, bf1.y);
                }
            }
        }

        // Epilogue: bias + relu + red.v4 (filters [4q, 4q+4))
#pragma unroll
        for (int mt = 0; mt < 2; ++mt) {
            const int ptl   = wid * 4 + mt * 2;
            const int seg_l = index[d * NPTS + bstart + ptl];
            const int seg_h = index[d * NPTS + bstart + ptl + 1];
            float* bl = g_seg + ((d * NSEG + seg_l) * BW + lr) * FOUT + 4 * q;
            float* bh = g_seg + ((d * NSEG + seg_h) * BW + lr) * FOUT + 4 * q;
            {
                const float v0 = fmaxf(acc[mt][0][0] + b0v, 0.f);
                const float v1 = fmaxf(acc[mt][0][1] + b1v, 0.f);
                const float v2 = fmaxf(acc[mt][1][0] + b2v, 0.f);
                const float v3 = fmaxf(acc[mt][1][1] + b3v, 0.f);
                asm volatile("red.global.add.v4.f32 [%0], {%1,%2,%3,%4};"
                             :: "l"(bl), "f"(v0), "f"(v1), "f"(v2), "f"(v3)
                             : "memory");
            }
            {
                const float v0 = fmaxf(acc[mt][0][2] + b0v, 0.f);
                const float v1 = fmaxf(acc[mt][0][3] + b1v, 0.f);
                const float v2 = fmaxf(acc[mt][1][2] + b2v, 0.f);
                const float v3 = fmaxf(acc[mt][1][3] + b3v, 0.f);
                asm volatile("red.global.add.v4.f32 [%0], {%1,%2,%3,%4};"
                             :: "l"(bh), "f"(v0), "f"(v1), "f"(v2), "f"(v3)
                             : "memory");
            }
        }

        // Commit prefetched tile into the other buffer, sync once
        if (t < TPC - 1) {
            store_tile(xs[cur ^ 1], tid, P);
            __syncthreads();
            cur ^= 1;
        }
    }
}

// ---------------------------------------------------------------------------
// Kernel 2: post conv (3,1) + relu, smem-tiled (3x less L1 traffic).
// grid (NSEG/32, NDIM), block 256; CTA covers 32 segments x 8 w.
// smem rows: local row = (sl_h)*8 + w, sl_h in [0,34); stride 20 floats (80B)
// -> conflict-free LDS.128 across 32 consecutive rows.
// ---------------------------------------------------------------------------
#define PSTR 20
__global__ void __launch_bounds__(256)
post_conv_kernel(const float* __restrict__ post_w, const float* __restrict__ post_b)
{
    __shared__ float ps[34 * 8 * PSTR];   // 21760B
    __shared__ float ws[768];
    __shared__ float bs[16];
    const int tid = threadIdx.x;
    const int d   = blockIdx.y;
    const int s0  = blockIdx.x * 32;

    for (int i = tid; i < 768; i += 256) ws[i] = post_w[d * 768 + i];
    if (tid < FOUT) bs[tid] = post_b[d * FOUT + tid];

    // Cooperative load: 272 rows x 4 float4 = 1088 tasks
    for (int i = tid; i < 34 * 8 * 4; i += 256) {
        const int row = i >> 2;
        const int tq  = i & 3;
        const int ss  = s0 - 1 + (row >> 3);
        const int w   = row & 7;
        float4 v = make_float4(0.f, 0.f, 0.f, 0.f);
        if ((unsigned)ss < NSEG)
            v = reinterpret_cast<const float4*>(
                g_seg + ((d * NSEG + ss) * BW + w) * FOUT)[tq];
        *reinterpret_cast<float4*>(ps + row * PSTR + tq * 4) = v;
    }
    __syncthreads();

    const int sl = tid >> 3;    // local segment 0..31
    const int w  = tid & 7;

    float acc[16];
#pragma unroll
    for (int f = 0; f < 16; ++f) acc[f] = 0.f;

#pragma unroll
    for (int a = 0; a < 3; ++a) {
        const float* src = ps + ((sl + a) * 8 + w) * PSTR;
#pragma unroll
        for (int cg = 0; cg < 4; ++cg) {
            const float4 x4 = *reinterpret_cast<const float4*>(src + cg * 4);
            const float* wr = ws + (a * 16 + cg * 4) * 16;
#pragma unroll
            for (int f = 0; f < 16; ++f) acc[f] += x4.x * wr[f];
#pragma unroll
            for (int f = 0; f < 16; ++f) acc[f] += x4.y * wr[16 + f];
#pragma unroll
            for (int f = 0; f < 16; ++f) acc[f] += x4.z * wr[32 + f];
#pragma unroll
            for (int f = 0; f < 16; ++f) acc[f] += x4.w * wr[48 + f];
        }
    }

    float4* dst = reinterpret_cast<float4*>(
        g_z + ((d * NSEG + s0 + sl) * BW + w) * FOUT);
#pragma unroll
    for (int fg = 0; fg < 4; ++fg) {
        float4 v;
        v.x = fmaxf(acc[fg * 4 + 0] + bs[fg * 4 + 0], 0.f);
        v.y = fmaxf(acc[fg * 4 + 1] + bs[fg * 4 + 1], 0.f);
        v.z = fmaxf(acc[fg * 4 + 2] + bs[fg * 4 + 2], 0.f);
        v.w = fmaxf(acc[fg * 4 + 3] + bs[fg * 4 + 3], 0.f);
        dst[fg] = v;
    }
}

// ---------------------------------------------------------------------------
// Kernel 3: Y[n,w,:] = sum_d g_z[d, index[d,n], w, :]
// Each thread: two n's -> 6 independent L2 loads in flight.
// ---------------------------------------------------------------------------
__global__ void __launch_bounds__(256)
gather_out_kernel(const int* __restrict__ index, float* __restrict__ out)
{
    const int gt = blockIdx.x * 256 + threadIdx.x;
    if (gt >= NPTS * BW * 2) return;
    const int n   = gt >> 5;
    const int rem = gt & 31;
    const int n2  = n + NPTS / 2;

    const int s0 = index[n],            t0 = index[n2];
    const int s1 = index[NPTS + n],     t1 = index[NPTS + n2];
    const int s2 = index[2 * NPTS + n], t2 = index[2 * NPTS + n2];

    const float4 a0 = reinterpret_cast<const float4*>(
        g_z + (size_t)s0 * (BW * FOUT))[rem];
    const float4 a1 = reinterpret_cast<const float4*>(
        g_z + (size_t)(NSEG + s1) * (BW * FOUT))[rem];
    const float4 a2 = reinterpret_cast<const float4*>(
        g_z + (size_t)(2 * NSEG + s2) * (BW * FOUT))[rem];
    const float4 c0 = reinterpret_cast<const float4*>(
        g_z + (size_t)t0 * (BW * FOUT))[rem];
    const float4 c1 = reinterpret_cast<const float4*>(
        g_z + (size_t)(NSEG + t1) * (BW * FOUT))[rem];
    const float4 c2 = reinterpret_cast<const float4*>(
        g_z + (size_t)(2 * NSEG + t2) * (BW * FOUT))[rem];

    float4 r;
    r.x = a0.x + a1.x + a2.x; r.y = a0.y + a1.y + a2.y;
    r.z = a0.z + a1.z + a2.z; r.w = a0.w + a1.w + a2.w;
    reinterpret_cast<float4*>(out)[n * 32 + rem] = r;

    float4 r2;
    r2.x = c0.x + c1.x + c2.x; r2.y = c0.y + c1.y + c2.y;
    r2.z = c0.z + c1.z + c2.z; r2.w = c0.w + c1.w + c2.w;
    reinterpret_cast<float4*>(out)[n2 * 32 + rem] = r2;
}

// ---------------------------------------------------------------------------
extern "C" void kernel_launch(void* const* d_in, const int* in_sizes, int n_in,
                              void* d_out, int out_size)
{
    const float* X      = (const float*)d_in[0];
    const int*   inv    = (const int*)  d_in[1];
    const int*   index  = (const int*)  d_in[2];
    const float* pre_w  = (const float*)d_in[3];
    const float* pre_b  = (const float*)d_in[4];
    const float* post_w = (const float*)d_in[5];
    const float* post_b = (const float*)d_in[6];
    float*       out    = (float*)      d_out;

    zero_seg_kernel<<<2048, 256>>>();
    weight_setup_kernel<<<16, 256>>>(pre_w, pre_b);

    dim3 g1(NBX, NDIM);
    pre_conv_mma_kernel<<<g1, T1>>>(X, inv, index);

    dim3 g2(NSEG / 32, NDIM);
    post_conv_kernel<<<g2, 256>>>(post_w, post_b);

    gather_out_kernel<<<(NPTS * BW * 2 + 255) / 256, 256>>>(index, out);
}

// round 13
// speedup vs baseline: 1.3743x; 1.3743x over previous
#include <cuda_runtime.h>
#include <cstdint>

// Problem constants
#define NPTS 100000
#define CIN  16
#define FOUT 16
#define BW   8
#define NDIM 3
#define NSEG 8192

// Pre-conv (fp16 mma.sync m16n8k16) tiling — persistent over tiles
#define PN    32                  // points per tile -> 256 output rows
#define T1    256                 // 8 warps; warp covers 32 rows (2 m16 tiles)
#define NTILE (NPTS / PN)         // 3125
#define TPC   5                   // tiles per CTA
#define NBX   (NTILE / TPC)       // 625
#define XS_WORDS (34 * 10 * 8)    // 2720
#define WB_WORDS (144 * 8)        // 1152

__device__ __forceinline__ uint32_t pack_f16x2(float lo, float hi) {
    uint32_t r;
    asm("cvt.rn.f16x2.f32 %0, %1, %2;" : "=r"(r) : "f"(hi), "f"(lo));
    return r;
}

#define MMA_F16(acc, a0, a1, a2, a3, b0, b1)                                   \
    asm("mma.sync.aligned.m16n8k16.row.col.f32.f16.f16.f32 "                   \
        "{%0,%1,%2,%3},{%4,%5,%6,%7},{%8,%9},{%0,%1,%2,%3};"                   \
        : "+f"(acc[0]), "+f"(acc[1]), "+f"(acc[2]), "+f"(acc[3])               \
        : "r"(a0), "r"(a1), "r"(a2), "r"(a3), "r"(b0), "r"(b1))

// Device scratch (static allocation — no cudaMalloc allowed)
__device__ float    g_seg[NDIM * NSEG * BW * FOUT];   // segment sums
__device__ float    g_z  [NDIM * NSEG * BW * FOUT];   // post-conv output
__device__ uint32_t g_wb [NDIM * WB_WORDS];           // permuted fp16 weights
__device__ float    g_bs [NDIM * FOUT];               // bias

// ---------------------------------------------------------------------------
// Kernel 0: zero the segment-sum scratch
// ---------------------------------------------------------------------------
__global__ void zero_seg_kernel() {
    const int total = NDIM * NSEG * BW * FOUT / 4;
    float4* p = reinterpret_cast<float4*>(g_seg);
    const float4 z = make_float4(0.f, 0.f, 0.f, 0.f);
    for (int i = blockIdx.x * blockDim.x + threadIdx.x; i < total;
         i += gridDim.x * blockDim.x)
        p[i] = z;
}

// ---------------------------------------------------------------------------
// Kernel 0b: permute + convert pre-conv weights to fp16 once.
// Storage row s = nt*8+n holds filter 4*(n>>1)+2*nt+(n&1); word j holds
// channel pair (c, c+1), c = j odd ? j+7 : j.
// ---------------------------------------------------------------------------
__global__ void weight_setup_kernel(const float* __restrict__ pre_w,
                                    const float* __restrict__ pre_b) {
    for (int gi = blockIdx.x * blockDim.x + threadIdx.x; gi < NDIM * WB_WORDS;
         gi += gridDim.x * blockDim.x) {
        const int d   = gi / WB_WORDS;
        const int i   = gi - d * WB_WORDS;
        const int tap = i >> 7;
        const int rem = i & 127;
        const int s   = rem >> 3;
        const int j   = rem & 7;
        const int nt  = s >> 3;
        const int n   = s & 7;
        const int fpm = 4 * (n >> 1) + 2 * nt + (n & 1);
        const int c   = (j & 1) ? (j + 7) : j;
        const int base = d * 2304 + tap * 256;
        g_wb[gi] = pack_f16x2(pre_w[base + c * 16 + fpm],
                              pre_w[base + (c + 1) * 16 + fpm]);
    }
    const int t = blockIdx.x * blockDim.x + threadIdx.x;
    if (t < NDIM * FOUT) g_bs[t] = pre_b[t];
}

// ---------------------------------------------------------------------------
// Kernel 1: gather X[inv] -> fp16 mma 3x3 conv -> relu -> atomic seg-sum
// grid (625, 3), block 256 (8 warps), PERSISTENT over 5 tiles each.
// (R11 structure — the proven-best configuration. Single xs buffer,
//  weights/bias loaded once per CTA, pad slots zeroed once. Per tile:
//  quad-cooperative gather -> sync -> 36 HMMA/warp -> sync -> red.v4.
//  New in R13: epilogue segment ids prefetched BEFORE the MMA loop.)
// ---------------------------------------------------------------------------
__global__ void __launch_bounds__(T1)
pre_conv_mma_kernel(const float* __restrict__ X, const int* __restrict__ inv,
                    const int* __restrict__ index)
{
    __shared__ uint32_t xs[XS_WORDS];
    __shared__ uint32_t wb[WB_WORDS];
    __shared__ float    bs[16];

    const int tid  = threadIdx.x;
    const int wid  = tid >> 5;
    const int lane = tid & 31;
    const int q    = lane & 3;    // fragment k-quad / D col group
    const int lr   = lane >> 2;   // fragment row / B n index (0..7)
    const int d    = blockIdx.y;

    // One-time: coalesced weight/bias load + pad-slot zeroing
    {
        const uint4* src = reinterpret_cast<const uint4*>(g_wb + d * WB_WORDS);
        uint4* dst = reinterpret_cast<uint4*>(wb);
        for (int i = tid; i < WB_WORDS / 4; i += T1) dst[i] = src[i];
        if (tid < FOUT) bs[tid] = g_bs[d * FOUT + tid];
        // w-pad slots (wslot 0 and 9): never written by gather
        for (int i = tid; i < 34 * 16; i += T1) {
            const int pt = i >> 4, rem = i & 15;
            const int wslot = (rem < 8) ? 0 : 9;
            xs[(pt * 10 + wslot) * 8 + (rem & 7)] = 0u;
        }
    }

#pragma unroll 1
    for (int t = 0; t < TPC; ++t) {
        const int tile   = blockIdx.x + NBX * t;
        const int bstart = tile * PN;

        // Edge tiles: zero the pt-halo rows the gather will skip
        if (tile == 0) {
            for (int i = tid; i < 64; i += T1)
                xs[(0 * 10 + ((i >> 3) + 1)) * 8 + (i & 7)] = 0u;
        }
        if (tile == NTILE - 1) {
            for (int i = tid; i < 64; i += T1)
                xs[(33 * 10 + ((i >> 3) + 1)) * 8 + (i & 7)] = 0u;
        }
        __syncthreads();   // also orders vs previous tile's mainloop reads

        // Quad-cooperative gather: 272 rows x 4 quarters = 1088 lane tasks
        for (int i = tid; i < 34 * 8 * 4; i += T1) {
            const int r  = i >> 2;          // row 0..271
            const int tq = i & 3;           // 16B quarter
            const int pt = r >> 3;
            const int w  = r & 7;
            const int gp = bstart - 1 + pt;
            if ((unsigned)gp >= NPTS) continue;
            const int idx = inv[(d * NPTS + gp) * BW + w];
            const float4 v = reinterpret_cast<const float4*>(X)[idx * 4 + tq];
            const int woff = (pt * 10 + w + 1) * 8 + 4 * (tq & 1) + (tq >> 1);
            xs[woff]     = pack_f16x2(v.x, v.y);
            xs[woff + 2] = pack_f16x2(v.z, v.w);
        }

        // Prefetch epilogue segment ids (drain under the MMA stream)
        int seg_l[2], seg_h[2];
#pragma unroll
        for (int mt = 0; mt < 2; ++mt) {
            const int ptl = wid * 4 + mt * 2;
            seg_l[mt] = index[d * NPTS + bstart + ptl];
            seg_h[mt] = index[d * NPTS + bstart + ptl + 1];
        }
        __syncthreads();

        // A-fragment bases: m-tile mt covers rows wid*32 + mt*16 + {lr, lr+8}
        int base_lo[2], base_hi[2];
#pragma unroll
        for (int mt = 0; mt < 2; ++mt) {
            const int ptl = wid * 4 + mt * 2;
            base_lo[mt] = (ptl * 10 + lr) * 8 + 2 * q;
            base_hi[mt] = base_lo[mt] + 80;
        }

        float acc[2][2][4];
#pragma unroll
        for (int mt = 0; mt < 2; ++mt)
#pragma unroll
            for (int nt = 0; nt < 2; ++nt)
#pragma unroll
                for (int i = 0; i < 4; ++i) acc[mt][nt][i] = 0.f;

#pragma unroll
        for (int a = 0; a < 3; ++a) {
#pragma unroll
            for (int b = 0; b < 3; ++b) {
                const int tap  = a * 3 + b;
                const int toff = (a * 10 + b) * 8;
                const uint2 bf0 = *reinterpret_cast<const uint2*>(
                    wb + (tap * 16 + lr) * 8 + 2 * q);
                const uint2 bf1 = *reinterpret_cast<const uint2*>(
                    wb + (tap * 16 + 8 + lr) * 8 + 2 * q);
#pragma unroll
                for (int mt = 0; mt < 2; ++mt) {
                    const uint2 alo = *reinterpret_cast<const uint2*>(
                        xs + base_lo[mt] + toff);
                    const uint2 ahi = *reinterpret_cast<const uint2*>(
                        xs + base_hi[mt] + toff);
                    MMA_F16(acc[mt][0], alo.x, ahi.x, alo.y, ahi.y, bf0.x, bf0.y);
                    MMA_F16(acc[mt][1], alo.x, ahi.x, alo.y, ahi.y, bf1.x, bf1.y);
                }
            }
        }
        __syncthreads();   // xs reads done; next tile may overwrite

        // Epilogue: bias + relu + ONE red.v4 per (mt, half); filters [4q,4q+4)
        const float b0v = bs[4 * q + 0], b1v = bs[4 * q + 1];
        const float b2v = bs[4 * q + 2], b3v = bs[4 * q + 3];
#pragma unroll
        for (int mt = 0; mt < 2; ++mt) {
            float* bl = g_seg + ((d * NSEG + seg_l[mt]) * BW + lr) * FOUT + 4 * q;
            float* bh = g_seg + ((d * NSEG + seg_h[mt]) * BW + lr) * FOUT + 4 * q;
            {
                const float v0 = fmaxf(acc[mt][0][0] + b0v, 0.f);
                const float v1 = fmaxf(acc[mt][0][1] + b1v, 0.f);
                const float v2 = fmaxf(acc[mt][1][0] + b2v, 0.f);
                const float v3 = fmaxf(acc[mt][1][1] + b3v, 0.f);
                asm volatile("red.global.add.v4.f32 [%0], {%1,%2,%3,%4};"
                             :: "l"(bl), "f"(v0), "f"(v1), "f"(v2), "f"(v3)
                             : "memory");
            }
            {
                const float v0 = fmaxf(acc[mt][0][2] + b0v, 0.f);
                const float v1 = fmaxf(acc[mt][0][3] + b1v, 0.f);
                const float v2 = fmaxf(acc[mt][1][2] + b2v, 0.f);
                const float v3 = fmaxf(acc[mt][1][3] + b3v, 0.f);
                asm volatile("red.global.add.v4.f32 [%0], {%1,%2,%3,%4};"
                             :: "l"(bh), "f"(v0), "f"(v1), "f"(v2), "f"(v3)
                             : "memory");
            }
        }
    }
}

// ---------------------------------------------------------------------------
// Kernel 2: post conv (3,1) + relu on g_seg -> g_z  (R11 direct-load version;
// block 128 / grid (512,3) for finer wave balance: ~10.4 CTAs/SM vs 5.2)
// ---------------------------------------------------------------------------
__global__ void __launch_bounds__(128)
post_conv_kernel(const float* __restrict__ post_w, const float* __restrict__ post_b)
{
    __shared__ float ws[768];
    __shared__ float bs[16];
    const int tid = threadIdx.x;
    const int d   = blockIdx.y;
    for (int i = tid; i < 768; i += 128) ws[i] = post_w[d * 768 + i];
    if (tid < FOUT) bs[tid] = post_b[d * FOUT + tid];
    __syncthreads();

    const int gt = blockIdx.x * 128 + tid;    // 0 .. NSEG*BW-1
    const int s  = gt >> 3;
    const int w  = gt & 7;

    float acc[16];
#pragma unroll
    for (int f = 0; f < 16; ++f) acc[f] = 0.f;

#pragma unroll
    for (int a = 0; a < 3; ++a) {
        const int ss = s + a - 1;
        if (ss < 0 || ss >= NSEG) continue;
        const float4* src = reinterpret_cast<const float4*>(
            g_seg + ((d * NSEG + ss) * BW + w) * FOUT);
#pragma unroll
        for (int cg = 0; cg < 4; ++cg) {
            const float4 x4 = src[cg];
            const float* wr = ws + (a * 16 + cg * 4) * 16;
#pragma unroll
            for (int f = 0; f < 16; ++f) acc[f] += x4.x * wr[f];
#pragma unroll
            for (int f = 0; f < 16; ++f) acc[f] += x4.y * wr[16 + f];
#pragma unroll
            for (int f = 0; f < 16; ++f) acc[f] += x4.z * wr[32 + f];
#pragma unroll
            for (int f = 0; f < 16; ++f) acc[f] += x4.w * wr[48 + f];
        }
    }

    float4* dst = reinterpret_cast<float4*>(g_z + ((d * NSEG + s) * BW + w) * FOUT);
#pragma unroll
    for (int fg = 0; fg < 4; ++fg) {
        float4 v;
        v.x = fmaxf(acc[fg * 4 + 0] + bs[fg * 4 + 0], 0.f);
        v.y = fmaxf(acc[fg * 4 + 1] + bs[fg * 4 + 1], 0.f);
        v.z = fmaxf(acc[fg * 4 + 2] + bs[fg * 4 + 2], 0.f);
        v.w = fmaxf(acc[fg * 4 + 3] + bs[fg * 4 + 3], 0.f);
        dst[fg] = v;
    }
}

// ---------------------------------------------------------------------------
// Kernel 3: Y[n,w,:] = sum_d g_z[d, index[d,n], w, :]
// Each thread: two n's -> 6 independent L2 loads in flight.
// ---------------------------------------------------------------------------
__global__ void __launch_bounds__(256)
gather_out_kernel(const int* __restrict__ index, float* __restrict__ out)
{
    const int gt = blockIdx.x * 256 + threadIdx.x;
    if (gt >= NPTS * BW * 2) return;
    const int n   = gt >> 5;
    const int rem = gt & 31;
    const int n2  = n + NPTS / 2;

    const int s0 = index[n],            t0 = index[n2];
    const int s1 = index[NPTS + n],     t1 = index[NPTS + n2];
    const int s2 = index[2 * NPTS + n], t2 = index[2 * NPTS + n2];

    const float4 a0 = reinterpret_cast<const float4*>(
        g_z + (size_t)s0 * (BW * FOUT))[rem];
    const float4 a1 = reinterpret_cast<const float4*>(
        g_z + (size_t)(NSEG + s1) * (BW * FOUT))[rem];
    const float4 a2 = reinterpret_cast<const float4*>(
        g_z + (size_t)(2 * NSEG + s2) * (BW * FOUT))[rem];
    const float4 c0 = reinterpret_cast<const float4*>(
        g_z + (size_t)t0 * (BW * FOUT))[rem];
    const float4 c1 = reinterpret_cast<const float4*>(
        g_z + (size_t)(NSEG + t1) * (BW * FOUT))[rem];
    const float4 c2 = reinterpret_cast<const float4*>(
        g_z + (size_t)(2 * NSEG + t2) * (BW * FOUT))[rem];

    float4 r;
    r.x = a0.x + a1.x + a2.x; r.y = a0.y + a1.y + a2.y;
    r.z = a0.z + a1.z + a2.z; r.w = a0.w + a1.w + a2.w;
    reinterpret_cast<float4*>(out)[n * 32 + rem] = r;

    float4 r2;
    r2.x = c0.x + c1.x + c2.x; r2.y = c0.y + c1.y + c2.y;
    r2.z = c0.z + c1.z + c2.z; r2.w = c0.w + c1.w + c2.w;
    reinterpret_cast<float4*>(out)[n2 * 32 + rem] = r2;
}

// ---------------------------------------------------------------------------
extern "C" void kernel_launch(void* const* d_in, const int* in_sizes, int n_in,
                              void* d_out, int out_size)
{
    const float* X      = (const float*)d_in[0];
    const int*   inv    = (const int*)  d_in[1];
    const int*   index  = (const int*)  d_in[2];
    const float* pre_w  = (const float*)d_in[3];
    const float* pre_b  = (const float*)d_in[4];
    const float* post_w = (const float*)d_in[5];
    const float* post_b = (const float*)d_in[6];
    float*       out    = (float*)      d_out;

    zero_seg_kernel<<<2048, 256>>>();
    weight_setup_kernel<<<16, 256>>>(pre_w, pre_b);

    dim3 g1(NBX, NDIM);
    pre_conv_mma_kernel<<<g1, T1>>>(X, inv, index);

    dim3 g2(NSEG * BW / 128, NDIM);
    post_conv_kernel<<<g2, 128>>>(post_w, post_b);

    gather_out_kernel<<<(NPTS * BW * 2 + 255) / 256, 256>>>(index, out);
}